// round 15
// baseline (speedup 1.0000x reference)
#include <cuda_runtime.h>

#define IN_DIM   8192
#define OUT_DIM  16384
#define TOPK     327
#define ROW_SPLITS 37                 // 16 * 37 = 592 = 4 * 148 SMs → one wave
#define ROWS_PER_SPLIT 222            // ceil(8192 / 37)
#define COL_BLOCKS 16
#define CNT_ONE  (1u << 20)
#define VAL_MASK 0xFFFFFu
#define BBLK     256                  // finalize blocks
#define BCOLS    (OUT_DIM / BBLK)     // 64 columns per finalize block
#define NCOARSE  65                   // coarse bins of 128 values (0..8192 → 0..64)
#define HIST_PAD (IN_DIM + 128)       // fine hist padded so cb=64 reads are in-bounds

__device__ __align__(16) unsigned g_overlap[OUT_DIM];  // packed [cnt|val]; self-resets
__device__ __align__(16) int      g_hist[HIST_PAD];    // fine bins; zeroed at gemv start
__device__ int                    g_coarse[NCOARSE];   // coarse bins; zeroed at gemv start
__device__ __align__(16) int      g_final[OUT_DIM];    // fully rewritten every launch

__device__ __forceinline__ int warp_incl_scan(int v) {
    int lane = threadIdx.x & 31;
#pragma unroll
    for (int o = 1; o < 32; o <<= 1) {
        int n = __shfl_up_sync(0xffffffffu, v, o);
        if (lane >= o) v += n;
    }
    return v;
}

// ---------------------------------------------------------------------------
// Kernel A: binarized GEMV (proven 42.8us form: per-slice ballot compaction,
// one wave of 592 blocks at 4/SM). Zeroes both histograms at start. Packed
// atomic accumulate; the 37th (last) arrival per column publishes g_final +
// fine & coarse histograms, then self-resets g_overlap[col].
// round(p) for p ~ U[0,1) under round-half-even == (p > 0.5f).
// ---------------------------------------------------------------------------
__global__ void __launch_bounds__(256, 4)
gemv_kernel(const float* __restrict__ p, const int* __restrict__ x) {
    __shared__ int s_act[ROWS_PER_SPLIT];
    __shared__ int s_wbase[8];
    __shared__ int s_na;

    int t    = threadIdx.x;
    int lane = t & 31;
    int w    = t >> 5;
    int bid  = blockIdx.y * COL_BLOCKS + blockIdx.x;

    // zero histograms for this launch (publishes can't happen before ~30us)
    if (bid < 33) {
        int i = bid * 256 + t;
        if (i < HIST_PAD) g_hist[i] = 0;
    } else if (bid == 33 && t < NCOARSE) {
        g_coarse[t] = 0;
    }

    int r0 = blockIdx.y * ROWS_PER_SPLIT;
    int r1 = min(r0 + ROWS_PER_SPLIT, IN_DIM);
    int n  = r1 - r0;

    // per-block ordered compaction of the x slice
    int flag = 0;
    if (t < n) flag = (x[r0 + t] != 0);
    unsigned m = __ballot_sync(0xffffffffu, flag);
    int pos = __popc(m & ((1u << lane) - 1u));
    if (lane == 0) s_wbase[w] = __popc(m);
    __syncthreads();
    if (t < 8) {
        int v = s_wbase[t];
        int inc = v;
#pragma unroll
        for (int o = 1; o < 8; o <<= 1) {
            int u = __shfl_up_sync(0xffu, inc, o);
            if (t >= o) inc += u;
        }
        s_wbase[t] = inc - v;
        if (t == 7) s_na = inc;
    }
    __syncthreads();
    if (flag) s_act[s_wbase[w] + pos] = r0 + t;
    __syncthreads();

    int na = s_na;
    int col = (blockIdx.x * blockDim.x + t) * 4;
    const float4* pc = reinterpret_cast<const float4*>(p + col);

    unsigned c0 = 0, c1 = 0, c2 = 0, c3 = 0;
    int r = 0;
    for (; r + 8 <= na; r += 8) {
        float4 v[8];
#pragma unroll
        for (int u = 0; u < 8; u++)
            v[u] = __ldcs(pc + (size_t)s_act[r + u] * (OUT_DIM / 4));
#pragma unroll
        for (int u = 0; u < 8; u++) {
            c0 += (v[u].x > 0.5f);
            c1 += (v[u].y > 0.5f);
            c2 += (v[u].z > 0.5f);
            c3 += (v[u].w > 0.5f);
        }
    }
    for (; r < na; r++) {
        float4 v0 = __ldcs(pc + (size_t)s_act[r] * (OUT_DIM / 4));
        c0 += (v0.x > 0.5f);
        c1 += (v0.y > 0.5f);
        c2 += (v0.z > 0.5f);
        c3 += (v0.w > 0.5f);
    }

    unsigned cc[4] = {c0, c1, c2, c3};
#pragma unroll
    for (int u = 0; u < 4; u++) {
        unsigned old = atomicAdd(&g_overlap[col + u], CNT_ONE + cc[u]);
        if ((old >> 20) == (ROW_SPLITS - 1)) {
            int fv = (int)((old & VAL_MASK) + cc[u]);
            g_final[col + u] = fv;
            atomicAdd(&g_hist[fv], 1);
            atomicAdd(&g_coarse[fv >> 7], 1);
            g_overlap[col + u] = 0u;      // self-reset: last toucher
        }
    }
}

// ---------------------------------------------------------------------------
// Kernel B: 256 fully independent blocks, 64 columns each. No atomics, no
// inter-block sync, no state reset. Two-level threshold: 65 coarse bins
// (serial walk) select one 128-bin fine window (one 128-element suffix scan)
// → exact (T,R). Then ties-before-segment from g_final and the output write,
// with exact jax.lax.top_k tie semantics (lower index first).
// ---------------------------------------------------------------------------
__global__ void __launch_bounds__(256)
finalize_kernel(float* __restrict__ out) {
    __shared__ int s_coarse[NCOARSE];
    __shared__ int s_fine[128];
    __shared__ int s_scan[128];
    __shared__ int s_w[8];
    __shared__ int s_cb, s_prev, s_T, s_R, s_pref;

    int t    = threadIdx.x;
    int lane = t & 31;
    int w    = t >> 5;
    int b    = blockIdx.x;
    int base = b * BCOLS;

    if (t < NCOARSE) s_coarse[t] = g_coarse[t];
    __syncthreads();

    // coarse walk (serial, 65 steps): find coarse bin containing T and the
    // exact count of values strictly above that bin.
    if (t == 0) {
        int running = 0;
        for (int j = NCOARSE - 1; j >= 0; j--) {
            int prev = running;
            running += s_coarse[j];
            if (prev < TOPK && running >= TOPK) {
                s_cb = j;
                s_prev = prev;           // count(> top of bin j)
                break;
            }
        }
    }
    __syncthreads();
    int cb = s_cb;
    int prevAbove = s_prev;

    // fine window load (zero-padded region above 8192 is never written)
    if (t < 128) s_fine[t] = g_hist[cb * 128 + t];
    __syncthreads();

    // 128-element suffix sums via reversed inclusive scan (4 warps)
    if (t < 128) s_scan[127 - t] = s_fine[t];
    __syncthreads();
    if (t < 128) {
        int v = s_scan[t];
        int inc = warp_incl_scan(v);
        if (lane == 31) s_w[w] = inc;
        __syncthreads();
        if (t == 0) {
            int s = 0;
#pragma unroll
            for (int j = 0; j < 4; j++) { int c = s_w[j]; s_w[j] = s; s += c; }
        }
        __syncthreads();
        s_scan[t] = inc + s_w[w];
    } else {
        __syncthreads();
        __syncthreads();
    }
    __syncthreads();

    // thread t<128 owns value v = cb*128 + t:
    //   count(>= v) = prevAbove + s_scan[127 - t]
    //   count(>  v) = prevAbove + (t==127 ? 0 : s_scan[126 - t])
    if (t < 128) {
        int ge = prevAbove + s_scan[127 - t];
        int gt = prevAbove + ((t == 127) ? 0 : s_scan[126 - t]);
        if (gt < TOPK && ge >= TOPK) {
            s_T = cb * 128 + t;
            s_R = TOPK - gt;
        }
    }
    __syncthreads();
    int T = s_T;
    int R = s_R;

    // ties at T strictly before this segment (index order), int4 reads
    int cnt = 0;
    {
        const int4* f4 = reinterpret_cast<const int4*>(g_final);
        int n4 = base >> 2;
        for (int i = t; i < n4; i += 256) {
            int4 v = f4[i];
            cnt += (v.x == T) + (v.y == T) + (v.z == T) + (v.w == T);
        }
    }
#pragma unroll
    for (int o = 16; o; o >>= 1) cnt += __shfl_down_sync(0xffffffffu, cnt, o);
    if (lane == 0) s_w[w] = cnt;
    __syncthreads();
    if (t == 0) {
        int s = 0;
#pragma unroll
        for (int j = 0; j < 8; j++) s += s_w[j];
        s_pref = s;
    }
    __syncthreads();

    // own 64 columns: warps 0 and 1, ballot-ordered tie ranks
    int v = 0, flag = 0;
    unsigned m = 0;
    if (t < BCOLS) {
        v = g_final[base + t];
        flag = (v == T);
    }
    if (w < 2) m = __ballot_sync(0xffffffffu, flag);
    if (t == 0) s_w[0] = __popc(m);          // warp-0 tie count for warp 1
    __syncthreads();

    if (t < BCOLS) {
        int rank = s_pref + ((w == 1) ? s_w[0] : 0) + __popc(m & ((1u << lane) - 1u));
        float val = 0.0f;
        if (v > T) val = 1.0f;
        else if (flag && rank < R) val = 1.0f;
        out[base + t] = val;
    }
}

extern "C" void kernel_launch(void* const* d_in, const int* in_sizes, int n_in,
                              void* d_out, int out_size) {
    const int*   x = (const int*)d_in[0];
    const float* p = (const float*)d_in[1];
    if (in_sizes[0] != IN_DIM) {
        x = (const int*)d_in[1];
        p = (const float*)d_in[0];
    }
    float* out = (float*)d_out;

    dim3 grid(COL_BLOCKS, ROW_SPLITS);
    gemv_kernel<<<grid, 256>>>(p, x);
    finalize_kernel<<<BBLK, 256>>>(out);
}